// round 1
// baseline (speedup 1.0000x reference)
#include <cuda_runtime.h>
#include <math.h>

#define D 768
#define E 8
#define F 3072
#define T_TOK 4096

// ---- scratch (no cudaMalloc allowed) ----
__device__ int   g_counts[E];
__device__ int   g_list[E * T_TOK];
__device__ float g_gates[E * T_TOK];
__device__ float g_H[(size_t)E * T_TOK * F];   // per-expert hidden activations

__global__ void init_kernel() {
    if (threadIdx.x < E) g_counts[threadIdx.x] = 0;
}

// One block per token. 8 warps: warp w computes gate/noise logits for expert w.
__global__ void router_kernel(const float* __restrict__ x,
                              const float* __restrict__ noise,
                              const float* __restrict__ Wg, const float* __restrict__ bg,
                              const float* __restrict__ Wn, const float* __restrict__ bn) {
    int t   = blockIdx.x;
    int tid = threadIdx.x;
    int w   = tid >> 5, lane = tid & 31;

    __shared__ float xs[D];
    __shared__ float noisy[E];

    const float* xr = x + (size_t)t * D;
    for (int i = tid; i < D; i += 256) xs[i] = xr[i];
    __syncthreads();

    float sg = 0.f, sn = 0.f;
    for (int i = lane; i < D; i += 32) {
        float xv = xs[i];
        sg += xv * Wg[i * E + w];
        sn += xv * Wn[i * E + w];
    }
    #pragma unroll
    for (int o = 16; o > 0; o >>= 1) {
        sg += __shfl_down_sync(0xffffffffu, sg, o);
        sn += __shfl_down_sync(0xffffffffu, sn, o);
    }
    if (lane == 0) {
        float lg = sg + bg[w];
        float ln = sn + bn[w];
        float sp = (ln > 20.f) ? ln : log1pf(expf(ln));   // softplus
        noisy[w] = lg + noise[(size_t)t * E + w] * sp;
    }
    __syncthreads();

    if (tid == 0) {
        // top-2 (first-occurrence tie-break, matches lax.top_k)
        int i1 = 0; float v1 = noisy[0];
        #pragma unroll
        for (int e = 1; e < E; e++) if (noisy[e] > v1) { v1 = noisy[e]; i1 = e; }
        int i2 = -1; float v2 = -3.4e38f;
        #pragma unroll
        for (int e = 0; e < E; e++) {
            if (e == i1) continue;
            if (noisy[e] > v2) { v2 = noisy[e]; i2 = e; }
        }
        // softmax over the two kept logits (others are -inf)
        float eb = expf(v2 - v1);
        float p1 = 1.f / (1.f + eb);
        float p2 = eb  / (1.f + eb);
        if (p1 > 1e-9f) {
            int pos = atomicAdd(&g_counts[i1], 1);
            g_list [i1 * T_TOK + pos] = t;
            g_gates[i1 * T_TOK + pos] = p1;
        }
        if (p2 > 1e-9f) {
            int pos = atomicAdd(&g_counts[i2], 1);
            g_list [i2 * T_TOK + pos] = t;
            g_gates[i2 * T_TOK + pos] = p2;
        }
    }
}

// Stage 1: H[e, m, :] = relu(x[tok_m] @ W1[e] + b1[e]).  Gathered-row GEMM.
// 64x64 tile, K-step 16, 256 threads, 4x4 per-thread register tile.
__global__ void __launch_bounds__(256) expert_gemm1(const float* __restrict__ x,
                                                    const float* __restrict__ W1,
                                                    const float* __restrict__ b1) {
    int e   = blockIdx.z;
    int cnt = g_counts[e];
    int m0  = blockIdx.y * 64;
    if (m0 >= cnt) return;
    int n0  = blockIdx.x * 64;

    __shared__ __align__(16) float As[16][64];
    __shared__ __align__(16) float Bs[16][64];
    __shared__ int toks[64];

    int tid = threadIdx.x;
    if (tid < 64) {
        int m = m0 + tid;
        toks[tid] = (m < cnt) ? g_list[e * T_TOK + m] : -1;
    }
    __syncthreads();

    int tx = tid & 15, ty = tid >> 4;
    float acc[4][4];
    #pragma unroll
    for (int i = 0; i < 4; i++)
        #pragma unroll
        for (int j = 0; j < 4; j++) acc[i][j] = 0.f;

    const float* Bb = W1 + (size_t)e * D * F;

    for (int k0 = 0; k0 < D; k0 += 16) {
        #pragma unroll
        for (int i = 0; i < 4; i++) {
            int idx = tid + i * 256;
            int k = idx & 15, m = idx >> 4;
            int tok = toks[m];
            As[k][m] = (tok >= 0) ? x[(size_t)tok * D + k0 + k] : 0.f;
        }
        #pragma unroll
        for (int i = 0; i < 4; i++) {
            int idx = tid + i * 256;
            int n = idx & 63, k = idx >> 6;
            Bs[k][n] = Bb[(size_t)(k0 + k) * F + n0 + n];
        }
        __syncthreads();
        #pragma unroll
        for (int k = 0; k < 16; k++) {
            float4 a = *(const float4*)&As[k][ty * 4];
            float4 b = *(const float4*)&Bs[k][tx * 4];
            float av[4] = {a.x, a.y, a.z, a.w};
            float bv[4] = {b.x, b.y, b.z, b.w};
            #pragma unroll
            for (int i = 0; i < 4; i++)
                #pragma unroll
                for (int j = 0; j < 4; j++)
                    acc[i][j] = fmaf(av[i], bv[j], acc[i][j]);
        }
        __syncthreads();
    }

    float bb[4];
    #pragma unroll
    for (int j = 0; j < 4; j++) bb[j] = b1[(size_t)e * F + n0 + tx * 4 + j];

    #pragma unroll
    for (int i = 0; i < 4; i++) {
        int m = m0 + ty * 4 + i;
        if (m < cnt) {
            float* Hp = &g_H[((size_t)e * T_TOK + m) * F + n0 + tx * 4];
            #pragma unroll
            for (int j = 0; j < 4; j++)
                Hp[j] = fmaxf(acc[i][j] + bb[j], 0.f);
        }
    }
}

// Stage 2: out[tok] += gate * (H[e, m, :] @ W2[e] + b2[e])
__global__ void __launch_bounds__(256) expert_gemm2(const float* __restrict__ W2,
                                                    const float* __restrict__ b2,
                                                    float* __restrict__ out) {
    int e   = blockIdx.z;
    int cnt = g_counts[e];
    int m0  = blockIdx.y * 64;
    if (m0 >= cnt) return;
    int n0  = blockIdx.x * 64;

    __shared__ __align__(16) float As[16][64];
    __shared__ __align__(16) float Bs[16][64];

    int tid = threadIdx.x;
    int tx = tid & 15, ty = tid >> 4;
    float acc[4][4];
    #pragma unroll
    for (int i = 0; i < 4; i++)
        #pragma unroll
        for (int j = 0; j < 4; j++) acc[i][j] = 0.f;

    const float* Bb = W2 + (size_t)e * F * D;

    for (int k0 = 0; k0 < F; k0 += 16) {
        #pragma unroll
        for (int i = 0; i < 4; i++) {
            int idx = tid + i * 256;
            int k = idx & 15, m = idx >> 4;
            As[k][m] = (m0 + m < cnt)
                ? g_H[((size_t)e * T_TOK + m0 + m) * F + k0 + k] : 0.f;
        }
        #pragma unroll
        for (int i = 0; i < 4; i++) {
            int idx = tid + i * 256;
            int n = idx & 63, k = idx >> 6;
            Bs[k][n] = Bb[(size_t)(k0 + k) * D + n0 + n];
        }
        __syncthreads();
        #pragma unroll
        for (int k = 0; k < 16; k++) {
            float4 a = *(const float4*)&As[k][ty * 4];
            float4 b = *(const float4*)&Bs[k][tx * 4];
            float av[4] = {a.x, a.y, a.z, a.w};
            float bv[4] = {b.x, b.y, b.z, b.w};
            #pragma unroll
            for (int i = 0; i < 4; i++)
                #pragma unroll
                for (int j = 0; j < 4; j++)
                    acc[i][j] = fmaf(av[i], bv[j], acc[i][j]);
        }
        __syncthreads();
    }

    #pragma unroll
    for (int i = 0; i < 4; i++) {
        int m = m0 + ty * 4 + i;
        if (m >= cnt) continue;
        int   tok = g_list [e * T_TOK + m];
        float g   = g_gates[e * T_TOK + m];
        #pragma unroll
        for (int j = 0; j < 4; j++) {
            int n = n0 + tx * 4 + j;
            float v = g * (acc[i][j] + b2[(size_t)e * D + n]);
            atomicAdd(&out[(size_t)tok * D + n], v);
        }
    }
}

extern "C" void kernel_launch(void* const* d_in, const int* in_sizes, int n_in,
                              void* d_out, int out_size) {
    const float* x     = (const float*)d_in[0];
    const float* noise = (const float*)d_in[1];
    const float* Wg    = (const float*)d_in[2];
    const float* bg    = (const float*)d_in[3];
    const float* Wn    = (const float*)d_in[4];
    const float* bn    = (const float*)d_in[5];
    const float* W1    = (const float*)d_in[6];
    const float* b1    = (const float*)d_in[7];
    const float* W2    = (const float*)d_in[8];
    const float* b2    = (const float*)d_in[9];
    float* out = (float*)d_out;

    cudaMemsetAsync(out, 0, (size_t)out_size * sizeof(float));
    init_kernel<<<1, 32>>>();
    router_kernel<<<T_TOK, 256>>>(x, noise, Wg, bg, Wn, bn);
    expert_gemm1<<<dim3(F / 64, T_TOK / 64, E), 256>>>(x, W1, b1);
    expert_gemm2<<<dim3(D / 64, T_TOK / 64, E), 256>>>(W2, b2, out);
}